// round 16
// baseline (speedup 1.0000x reference)
#include <cuda_runtime.h>
#include <cuda_bf16.h>
#include <cstdint>

#define KN     8192
#define KD     8
#define NSEG   8
#define SEGSZ  1024
#define NTILE  64            // 128-row j-tiles per matrix
#define TW     4             // words per 128-bit mask
#define DOMB   288           // per matrix: sum_{s=0..7}(8s+8)

// Device-global scratch. Statics start zeroed; every consumer re-zeroes or
// fully overwrites what it reads -> graph replays are deterministic.
__device__ unsigned g_keys0[2][KN];            // d0 sortable keys, segment-sorted
__device__ int      g_kidx0[2][KN];            // original row per seg-sorted pos
__device__ int      g_perm[2][KN];             // d0-rank -> original row
__device__ unsigned g_pk[2][KN][8];            // per d0-rank: 8 sortable keys
__device__ unsigned g_sr[2][NTILE][7][128];    // per tile/dim: ascending keys
__device__ unsigned g_B[2][NTILE][7][129][TW]; // cumulative bitmask tables
__device__ int      g_counts[2 * KN];          // per d0-rank dominated counts
__device__ int      g_hd[KN];                  // signed diff histogram (A - B)
__device__ unsigned g_ctr;                     // finh arrival counter

__device__ __forceinline__ unsigned f2sortable(float f) {
    unsigned u = __float_as_uint(f);
    return (u & 0x80000000u) ? ~u : (u | 0x80000000u);
}

// ---------------------------------------------------------------------------
// S1) bitonic-sort 1024-element segments of dim 0 only. grid = (NSEG, 2).
// ---------------------------------------------------------------------------
__global__ __launch_bounds__(256) void kdm_sort_seg(const float* __restrict__ X,
                                                    const float* __restrict__ Xh) {
    const int m = blockIdx.y;
    const float* __restrict__ src = m ? Xh : X;
    __shared__ unsigned long long s[SEGSZ];   // 8 KB
    const int t  = threadIdx.x;
    const int e0 = blockIdx.x * SEGSZ;

    unsigned long long v[4];
    #pragma unroll
    for (int q = 0; q < 4; q++) {
        const int idx = q * 256 + t;
        v[q] = ((unsigned long long)f2sortable(src[(size_t)(e0 + idx) * KD]) << 32)
               | (unsigned)(e0 + idx);
    }

    #pragma unroll
    for (int k = 2; k <= SEGSZ; k <<= 1) {
        int j = k >> 1;
        #pragma unroll
        for (int jj = 512; jj >= 256; jj >>= 1) {
            if (jj <= (k >> 1)) {
                const int dq = jj >> 8;
                #pragma unroll
                for (int qa = 0; qa < 4; qa++) {
                    if ((qa & dq) == 0) {
                        const int qb = qa | dq;
                        const bool up = (((qa * 256 + t) & k) == 0);
                        const unsigned long long a = v[qa], b = v[qb];
                        if ((a > b) == up) { v[qa] = b; v[qb] = a; }
                    }
                }
                j = jj >> 1;
            }
        }
        while (j >= 32) {
            #pragma unroll
            for (int q = 0; q < 4; q++) s[q * 256 + t] = v[q];
            __syncthreads();
            unsigned long long p[4];
            #pragma unroll
            for (int q = 0; q < 4; q++) p[q] = s[q * 256 + (t ^ j)];
            __syncthreads();
            #pragma unroll
            for (int q = 0; q < 4; q++) {
                const bool up   = (((q * 256 + t) & k) == 0);
                const bool low  = (t & j) == 0;
                const bool keepmin = (low == up);
                const bool omin = (p[q] < v[q]);
                v[q] = (keepmin == omin) ? p[q] : v[q];
            }
            j >>= 1;
        }
        #pragma unroll
        for (int jj = 16; jj >= 1; jj >>= 1) {
            if (jj <= (k >> 1)) {
                #pragma unroll
                for (int q = 0; q < 4; q++) {
                    const unsigned long long o = __shfl_xor_sync(0xffffffffu, v[q], jj);
                    const bool up   = (((q * 256 + t) & k) == 0);
                    const bool low  = (t & jj) == 0;
                    const bool keepmin = (low == up);
                    const bool omin = (o < v[q]);
                    v[q] = (keepmin == omin) ? o : v[q];
                }
            }
        }
    }

    #pragma unroll
    for (int q = 0; q < 4; q++) {
        const unsigned long long r = v[q];
        g_keys0[m][e0 + q * 256 + t] = (unsigned)(r >> 32);
        g_kidx0[m][e0 + q * 256 + t] = (int)(unsigned)r;
    }
}

// ---------------------------------------------------------------------------
// S2) global d0 rank via cross-segment binary search -> permutation.
// ---------------------------------------------------------------------------
__global__ __launch_bounds__(256) void kdm_rank() {
    const int m = blockIdx.y;
    const int e = blockIdx.x * 256 + threadIdx.x;
    const int s = e >> 10;
    const int pos = e & (SEGSZ - 1);

    cudaGridDependencySynchronize();

    __shared__ unsigned sk[KN];   // 32 KB
    for (int k = threadIdx.x; k < KN; k += 256) sk[k] = g_keys0[m][k];
    __syncthreads();

    const unsigned key = sk[e];
    int rank = pos;
    #pragma unroll
    for (int t = 0; t < NSEG; t++) {
        if (t == s) continue;
        const unsigned* seg = sk + t * SEGSZ;
        int lo = 0, hi = SEGSZ;
        if (t < s) {  // count <= key
            while (lo < hi) { const int mid = (lo + hi) >> 1; if (seg[mid] <= key) lo = mid + 1; else hi = mid; }
        } else {      // count < key
            while (lo < hi) { const int mid = (lo + hi) >> 1; if (seg[mid] <  key) lo = mid + 1; else hi = mid; }
        }
        rank += lo;
    }
    g_perm[m][rank] = g_kidx0[m][e];
}

// ---------------------------------------------------------------------------
// P) per (tile, dim 1..7): ascending key list + cumulative bitmask table
//    (index tie-break -> bijective positions). The d==1 plane also packs
//    each i_rank's 8 sortable keys into g_pk. grid = (NTILE, 7, 2), 128 thr.
// ---------------------------------------------------------------------------
__global__ __launch_bounds__(128) void kdm_prep(const float* __restrict__ X,
                                                const float* __restrict__ Xh) {
    const int tt = blockIdx.x;
    const int dd = blockIdx.y + 1;       // dims 1..7
    const int m  = blockIdx.z;
    const int k  = threadIdx.x;
    const float* __restrict__ src = m ? Xh : X;

    cudaGridDependencySynchronize();     // wait for kdm_rank's g_perm

    __shared__ unsigned      skey[128];
    __shared__ unsigned char pos[128];

    const int row = g_perm[m][tt * 128 + k];
    const unsigned mykey = f2sortable(src[(size_t)row * KD + dd]);
    skey[k] = mykey;
    __syncthreads();

    int o = 0;
    #pragma unroll 8
    for (int r = 0; r < 128; r++)
        o += (skey[r] < mykey) || (skey[r] == mykey && r < k);
    pos[k] = (unsigned char)o;
    g_sr[m][tt][dd - 1][o] = mykey;      // scatter -> ascending (bijective)
    __syncthreads();

    // thread p = k builds B[p] (rows whose position < p)
    unsigned acc[TW] = {0, 0, 0, 0};
    #pragma unroll 8
    for (int r = 0; r < 128; r++)
        acc[r >> 5] |= (unsigned)(pos[r] < k) << (r & 31);
    #pragma unroll
    for (int w = 0; w < TW; w++) g_B[m][tt][dd - 1][k][w] = acc[w];
    if (k == 0) {
        #pragma unroll
        for (int w = 0; w < TW; w++) g_B[m][tt][dd - 1][128][w] = 0xFFFFFFFFu;
    }

    if (dd == 1) {   // pack this i_rank's 8 keys (coalesced read in dom)
        const float4 r0 = reinterpret_cast<const float4*>(src + (size_t)row * KD)[0];
        const float4 r1 = reinterpret_cast<const float4*>(src + (size_t)row * KD)[1];
        uint4 a, b;
        a.x = f2sortable(r0.x); a.y = f2sortable(r0.y);
        a.z = f2sortable(r0.z); a.w = f2sortable(r0.w);
        b.x = f2sortable(r1.x); b.y = f2sortable(r1.y);
        b.z = f2sortable(r1.z); b.w = f2sortable(r1.w);
        reinterpret_cast<uint4*>(&g_pk[m][tt * 128 + k][0])[0] = a;
        reinterpret_cast<uint4*>(&g_pk[m][tt * 128 + k][0])[1] = b;
    }
}

// ---------------------------------------------------------------------------
// D) bitset dominance. Block = (1024-rank i-strip) x (128-row j-tile).
//    Strip s has 8s+8 tiles; start(s) = 4s(s+1). Per i: 7 searches, then
//    AND of 7 mask rows (LDS.128) with the d0 prefix mask, popcount.
// ---------------------------------------------------------------------------
__global__ __launch_bounds__(256) void kdm_dom() {
    const int m = blockIdx.y;
    const int bx = blockIdx.x;
    int s = 0;
    while (4 * (s + 1) * (s + 2) <= bx) s++;
    const int tt = bx - 4 * s * (s + 1);
    const int tid = threadIdx.x;

    cudaGridDependencySynchronize();

    __shared__ __align__(16) unsigned sB[7][129][TW];  // 14448 B
    __shared__ unsigned ssr[7][128];                   // 3584 B

    {   // cooperative slab loads (contiguous per (m,tt))
        const unsigned* gb = &g_B[m][tt][0][0][0];
        unsigned* sb = &sB[0][0][0];
        for (int idx = tid; idx < 7 * 129 * TW; idx += 256) sb[idx] = gb[idx];
        const unsigned* gr = &g_sr[m][tt][0][0];
        unsigned* sr = &ssr[0][0];
        for (int idx = tid; idx < 7 * 128; idx += 256) sr[idx] = gr[idx];
    }
    __syncthreads();

    #pragma unroll
    for (int p = 0; p < 4; p++) {
        const int i_rank = (s << 10) + (p << 8) + tid;
        const uint4 ka = reinterpret_cast<const uint4*>(&g_pk[m][i_rank][0])[0];
        const uint4 kb = reinterpret_cast<const uint4*>(&g_pk[m][i_rank][0])[1];
        const unsigned key[7] = {ka.y, ka.z, ka.w, kb.x, kb.y, kb.z, kb.w};

        int pd[7];
        #pragma unroll
        for (int d = 0; d < 7; d++) {
            int k = 0;
            #pragma unroll
            for (int st = 64; st >= 1; st >>= 1)
                k += (ssr[d][k + st - 1] < key[d]) ? st : 0;
            k += (ssr[d][k] < key[d]);       // count of tile keys < key
            pd[d] = k;
        }

        int L = i_rank - (tt << 7);
        L = (L < 0) ? 0 : (L > 128 ? 128 : L);

        const uint4 m0 = *reinterpret_cast<const uint4*>(&sB[0][pd[0]][0]);
        const uint4 m1 = *reinterpret_cast<const uint4*>(&sB[1][pd[1]][0]);
        const uint4 m2 = *reinterpret_cast<const uint4*>(&sB[2][pd[2]][0]);
        const uint4 m3 = *reinterpret_cast<const uint4*>(&sB[3][pd[3]][0]);
        const uint4 m4 = *reinterpret_cast<const uint4*>(&sB[4][pd[4]][0]);
        const uint4 m5 = *reinterpret_cast<const uint4*>(&sB[5][pd[5]][0]);
        const uint4 m6 = *reinterpret_cast<const uint4*>(&sB[6][pd[6]][0]);

        unsigned pm[TW];
        #pragma unroll
        for (int w = 0; w < TW; w++) {
            const int rem = L - (w << 5);
            pm[w] = (rem <= 0) ? 0u : (rem >= 32 ? 0xFFFFFFFFu : ((1u << rem) - 1u));
        }

        int cnt = 0;
        cnt += __popc(m0.x & m1.x & m2.x & m3.x & m4.x & m5.x & m6.x & pm[0]);
        cnt += __popc(m0.y & m1.y & m2.y & m3.y & m4.y & m5.y & m6.y & pm[1]);
        cnt += __popc(m0.z & m1.z & m2.z & m3.z & m4.z & m5.z & m6.z & pm[2]);
        cnt += __popc(m0.w & m1.w & m2.w & m3.w & m4.w & m5.w & m6.w & pm[3]);

        atomicAdd(&g_counts[m * KN + i_rank], cnt);
    }
}

// ---------------------------------------------------------------------------
// FH) fused histogram + finalize (proven). Last-arriving block runs the W1
//     scan; resets scratch for the next graph replay.
// ---------------------------------------------------------------------------
__global__ __launch_bounds__(1024) void kdm_finh(float* __restrict__ out) {
    const int tid = threadIdx.x, lane = tid & 31, wid = tid >> 5;

    cudaGridDependencySynchronize();

    {   // histogram phase
        const int slot = blockIdx.x * 1024 + tid;
        const int v = g_counts[slot];          // dominated count in [0, 8191]
        g_counts[slot] = 0;
        const int delta = (slot >= KN) ? -1 : 1;
        const unsigned mask = __match_any_sync(0xffffffffu, v);
        if ((int)(__ffs(mask) - 1) == lane)
            atomicAdd(&g_hd[v], delta * __popc(mask));
    }

    __threadfence();
    __syncthreads();
    __shared__ bool s_last;
    if (tid == 0) s_last = (atomicAdd(&g_ctr, 1u) == gridDim.x - 1);
    __syncthreads();
    if (!s_last) return;
    __threadfence();

    __shared__ int wsum[32];
    const int base = tid * 8;
    int d[8], tot = 0;
    #pragma unroll
    for (int k = 0; k < 8; k++) {
        d[k] = g_hd[base + k];
        g_hd[base + k] = 0;
        tot += d[k];
    }

    int v = tot;
    #pragma unroll
    for (int off = 1; off < 32; off <<= 1) {
        const int n = __shfl_up_sync(0xffffffffu, v, off);
        if (lane >= off) v += n;
    }
    if (lane == 31) wsum[wid] = v;
    __syncthreads();
    if (wid == 0) {
        int w = wsum[lane];
        #pragma unroll
        for (int off = 1; off < 32; off <<= 1) {
            const int n = __shfl_up_sync(0xffffffffu, w, off);
            if (lane >= off) w += n;
        }
        wsum[lane] = w;
    }
    __syncthreads();

    const int excl = v - tot + (wid ? wsum[wid - 1] : 0);
    int run = excl, acc = 0;
    #pragma unroll
    for (int k = 0; k < 8; k++) {
        run += d[k];
        acc += (run >= 0) ? run : -run;
    }

    #pragma unroll
    for (int off = 16; off; off >>= 1) acc += __shfl_down_sync(0xffffffffu, acc, off);
    __syncthreads();
    if (lane == 0) wsum[wid] = acc;
    __syncthreads();
    if (wid == 0) {
        int r = wsum[lane];
        #pragma unroll
        for (int off = 16; off; off >>= 1) r += __shfl_down_sync(0xffffffffu, r, off);
        if (lane == 0) {
            out[0] = (float)r / ((float)KN * (float)(KN - 1));
            g_ctr = 0;   // reset for next graph replay
        }
    }
}

// ---------------------------------------------------------------------------
template <typename F, typename... Args>
static void launch_pdl(F f, dim3 grid, dim3 block, Args... args) {
    cudaLaunchConfig_t cfg = {};
    cfg.gridDim  = grid;
    cfg.blockDim = block;
    cfg.dynamicSmemBytes = 0;
    cfg.stream = 0;
    cudaLaunchAttribute attr[1];
    attr[0].id = cudaLaunchAttributeProgrammaticStreamSerialization;
    attr[0].val.programmaticStreamSerializationAllowed = 1;
    cfg.attrs = attr;
    cfg.numAttrs = 1;
    cudaLaunchKernelEx(&cfg, f, args...);
}

extern "C" void kernel_launch(void* const* d_in, const int* in_sizes, int n_in,
                              void* d_out, int out_size) {
    const float* X  = (const float*)d_in[0];
    const float* Xh = (const float*)d_in[1];
    float* out = (float*)d_out;

    kdm_sort_seg<<<dim3(NSEG, 2), 256>>>(X, Xh);
    launch_pdl(kdm_rank, dim3(KN / 256, 2), dim3(256));
    launch_pdl(kdm_prep, dim3(NTILE, 7, 2), dim3(128), X, Xh);
    launch_pdl(kdm_dom,  dim3(DOMB, 2),     dim3(256));
    launch_pdl(kdm_finh, dim3(2 * KN / 1024), dim3(1024), out);
}

// round 17
// speedup vs baseline: 1.1078x; 1.1078x over previous
#include <cuda_runtime.h>
#include <cuda_bf16.h>
#include <cstdint>

#define KN     8192
#define KD     8
#define NSEG   8
#define SEGSZ  1024
#define NTILE  64            // 128-row j-tiles per matrix
#define TW     4             // words per 128-bit mask
#define DOMB   288           // per matrix: sum_{s=0..7}(8s+8)

// Device-global scratch. Statics start zeroed; every consumer re-zeroes or
// fully overwrites what it reads -> graph replays are deterministic.
__device__ unsigned       g_keys[16][KN];           // [m*8+d] segment-sorted keys
__device__ int            g_kidx[16][KN];           // original row per seg-sorted pos
__device__ unsigned short g_rank[2][KN][8];         // per-row per-dim global rank
__device__ int            g_perm[2][KN];            // d0-rank -> original row
__device__ uint4          g_pr[2][KN];              // per d0-rank: 8 packed u16 ranks
__device__ unsigned short g_sr[2][NTILE][7][128];   // per tile/dim: ascending member ranks
__device__ unsigned char  g_lut[2][NTILE][7][256];  // rank-window LUT (32-wide windows)
__device__ unsigned       g_B[2][NTILE][7][129][TW];// cumulative bitmask tables
__device__ int            g_counts[2 * KN];         // per d0-rank dominated counts
__device__ int            g_hd[KN];                 // signed diff histogram (A - B)
__device__ unsigned       g_ctr;                    // finh arrival counter

__device__ __forceinline__ unsigned f2sortable(float f) {
    unsigned u = __float_as_uint(f);
    return (u & 0x80000000u) ? ~u : (u | 0x80000000u);
}

// ---------------------------------------------------------------------------
// S1) bitonic-sort 1024-element segments of every (m, d) plane (proven).
// ---------------------------------------------------------------------------
__global__ __launch_bounds__(256) void kdm_sort_seg(const float* __restrict__ X,
                                                    const float* __restrict__ Xh) {
    const int md = blockIdx.y;
    const int d  = md & 7;
    const float* __restrict__ src = (md >> 3) ? Xh : X;
    __shared__ unsigned long long s[SEGSZ];   // 8 KB
    const int t  = threadIdx.x;
    const int e0 = blockIdx.x * SEGSZ;

    unsigned long long v[4];
    #pragma unroll
    for (int q = 0; q < 4; q++) {
        const int idx = q * 256 + t;
        v[q] = ((unsigned long long)f2sortable(src[(size_t)(e0 + idx) * KD + d]) << 32)
               | (unsigned)(e0 + idx);
    }

    #pragma unroll
    for (int k = 2; k <= SEGSZ; k <<= 1) {
        int j = k >> 1;
        #pragma unroll
        for (int jj = 512; jj >= 256; jj >>= 1) {
            if (jj <= (k >> 1)) {
                const int dq = jj >> 8;
                #pragma unroll
                for (int qa = 0; qa < 4; qa++) {
                    if ((qa & dq) == 0) {
                        const int qb = qa | dq;
                        const bool up = (((qa * 256 + t) & k) == 0);
                        const unsigned long long a = v[qa], b = v[qb];
                        if ((a > b) == up) { v[qa] = b; v[qb] = a; }
                    }
                }
                j = jj >> 1;
            }
        }
        while (j >= 32) {
            #pragma unroll
            for (int q = 0; q < 4; q++) s[q * 256 + t] = v[q];
            __syncthreads();
            unsigned long long p[4];
            #pragma unroll
            for (int q = 0; q < 4; q++) p[q] = s[q * 256 + (t ^ j)];
            __syncthreads();
            #pragma unroll
            for (int q = 0; q < 4; q++) {
                const bool up   = (((q * 256 + t) & k) == 0);
                const bool low  = (t & j) == 0;
                const bool keepmin = (low == up);
                const bool omin = (p[q] < v[q]);
                v[q] = (keepmin == omin) ? p[q] : v[q];
            }
            j >>= 1;
        }
        #pragma unroll
        for (int jj = 16; jj >= 1; jj >>= 1) {
            if (jj <= (k >> 1)) {
                #pragma unroll
                for (int q = 0; q < 4; q++) {
                    const unsigned long long o = __shfl_xor_sync(0xffffffffu, v[q], jj);
                    const bool up   = (((q * 256 + t) & k) == 0);
                    const bool low  = (t & jj) == 0;
                    const bool keepmin = (low == up);
                    const bool omin = (o < v[q]);
                    v[q] = (keepmin == omin) ? o : v[q];
                }
            }
        }
    }

    #pragma unroll
    for (int q = 0; q < 4; q++) {
        const unsigned long long r = v[q];
        g_keys[md][e0 + q * 256 + t] = (unsigned)(r >> 32);
        g_kidx[md][e0 + q * 256 + t] = (int)(unsigned)r;
    }
}

// ---------------------------------------------------------------------------
// S2) global rank per plane via cross-segment binary search (proven).
//     Writes g_rank; d==0 also writes the d0 permutation.
// ---------------------------------------------------------------------------
__global__ __launch_bounds__(256) void kdm_rank() {
    const int md = blockIdx.y;
    const int m  = md >> 3;
    const int d  = md & 7;
    const int e  = blockIdx.x * 256 + threadIdx.x;
    const int s  = e >> 10;
    const int pos = e & (SEGSZ - 1);

    cudaGridDependencySynchronize();

    __shared__ unsigned sk[KN];   // 32 KB
    for (int k = threadIdx.x; k < KN; k += 256) sk[k] = g_keys[md][k];
    __syncthreads();

    const unsigned key = sk[e];
    int rank = pos;
    #pragma unroll
    for (int t = 0; t < NSEG; t++) {
        if (t == s) continue;
        const unsigned* seg = sk + t * SEGSZ;
        int lo = 0, hi = SEGSZ;
        if (t < s) {  // count <= key
            while (lo < hi) { const int mid = (lo + hi) >> 1; if (seg[mid] <= key) lo = mid + 1; else hi = mid; }
        } else {      // count < key
            while (lo < hi) { const int mid = (lo + hi) >> 1; if (seg[mid] <  key) lo = mid + 1; else hi = mid; }
        }
        rank += lo;
    }

    const int row = g_kidx[md][e];
    g_rank[m][row][d] = (unsigned short)rank;
    if (d == 0) g_perm[m][rank] = row;
}

// ---------------------------------------------------------------------------
// P) per (tile, dim 1..7): ascending member-rank list, 32-rank-window LUT,
//    and cumulative bitmask table. The dd==1 plane also packs each i_rank's
//    8 ranks into g_pr. grid = (NTILE, 7, 2), 128 threads.
// ---------------------------------------------------------------------------
__global__ __launch_bounds__(128) void kdm_prep() {
    const int tt = blockIdx.x;
    const int dd = blockIdx.y + 1;       // dims 1..7
    const int m  = blockIdx.z;
    const int k  = threadIdx.x;

    cudaGridDependencySynchronize();     // wait for kdm_rank

    __shared__ unsigned short ranks[128];
    __shared__ unsigned char  pos[128];
    __shared__ unsigned short ssr_s[136];   // +8 sentinel pad

    const int row = g_perm[m][tt * 128 + k];
    const unsigned short myrank = g_rank[m][row][dd];
    ranks[k] = myrank;
    if (k < 8) ssr_s[128 + k] = 0xFFFF;
    __syncthreads();

    int o = 0;
    #pragma unroll 8
    for (int r = 0; r < 128; r++) o += (ranks[r] < myrank);   // ranks distinct
    pos[k] = (unsigned char)o;
    ssr_s[o] = myrank;
    g_sr[m][tt][dd - 1][o] = myrank;
    __syncthreads();

    // bitmask table: thread p = k builds B[p] (rows with tile-d-position < p)
    unsigned acc[TW] = {0, 0, 0, 0};
    #pragma unroll 8
    for (int r = 0; r < 128; r++)
        acc[r >> 5] |= (unsigned)(pos[r] < k) << (r & 31);
    #pragma unroll
    for (int w = 0; w < TW; w++) g_B[m][tt][dd - 1][k][w] = acc[w];
    if (k == 0) {
        #pragma unroll
        for (int w = 0; w < TW; w++) g_B[m][tt][dd - 1][128][w] = 0xFFFFFFFFu;
    }

    // LUT: entry q = lower_bound(ssr_s, q<<5); thread k does q = k, k+128
    #pragma unroll
    for (int h = 0; h < 2; h++) {
        const int q = k + h * 128;
        const unsigned short thr = (unsigned short)(q << 5);
        int lo = 0;
        #pragma unroll
        for (int st = 64; st >= 1; st >>= 1)
            lo += (ssr_s[lo + st - 1] < thr) ? st : 0;
        lo += (ssr_s[lo] < thr);
        g_lut[m][tt][dd - 1][q] = (unsigned char)lo;
    }

    if (dd == 1)   // pack this i_rank's 8 ranks (coalesced read in dom)
        g_pr[m][tt * 128 + k] = *reinterpret_cast<const uint4*>(&g_rank[m][row][0]);
}

// ---------------------------------------------------------------------------
// D) bitset dominance with LUT-accelerated position lookup.
//    Block = (1024-rank i-strip) x (128-row j-tile); strip s has 8s+8 tiles.
// ---------------------------------------------------------------------------
__global__ __launch_bounds__(256) void kdm_dom() {
    const int m = blockIdx.y;
    const int bx = blockIdx.x;
    int s = 0;
    while (4 * (s + 1) * (s + 2) <= bx) s++;
    const int tt = bx - 4 * s * (s + 1);
    const int tid = threadIdx.x;

    cudaGridDependencySynchronize();

    __shared__ __align__(16) unsigned sB[7][129][TW];   // 14448 B
    __shared__ unsigned short ssr_f[7 * 136];           // 1904 B (+sentinels)
    __shared__ unsigned char  slut[7 * 256];            // 1792 B

    {   // cooperative slab loads (contiguous source layouts)
        const unsigned* gb = &g_B[m][tt][0][0][0];
        unsigned* sb = &sB[0][0][0];
        for (int idx = tid; idx < 7 * 129 * TW; idx += 256) sb[idx] = gb[idx];
        const unsigned short* gr = &g_sr[m][tt][0][0];
        for (int idx = tid; idx < 7 * 128; idx += 256)
            ssr_f[(idx >> 7) * 136 + (idx & 127)] = gr[idx];
        if (tid < 7 * 8) ssr_f[(tid >> 3) * 136 + 128 + (tid & 7)] = 0xFFFF;
        const unsigned* gl = (const unsigned*)&g_lut[m][tt][0][0];
        unsigned* sl = (unsigned*)slut;
        for (int idx = tid; idx < 7 * 256 / 4; idx += 256) sl[idx] = gl[idx];
    }
    __syncthreads();

    #pragma unroll
    for (int p = 0; p < 4; p++) {
        const int i_rank = (s << 10) + (p << 8) + tid;
        const uint4 pk = g_pr[m][i_rank];
        const unsigned r_[7] = {pk.x >> 16, pk.y & 0xffffu, pk.y >> 16,
                                pk.z & 0xffffu, pk.z >> 16,
                                pk.w & 0xffffu, pk.w >> 16};

        int pd[7];
        #pragma unroll
        for (int d = 0; d < 7; d++) {
            const unsigned r = r_[d];
            int k = slut[d * 256 + (r >> 5)];
            const unsigned short* sr = &ssr_f[d * 136];
            while (sr[k] < r) k++;          // expected ~0.5 iterations
            pd[d] = k;
        }

        int L = i_rank - (tt << 7);
        L = (L < 0) ? 0 : (L > 128 ? 128 : L);

        const uint4 m0 = *reinterpret_cast<const uint4*>(&sB[0][pd[0]][0]);
        const uint4 m1 = *reinterpret_cast<const uint4*>(&sB[1][pd[1]][0]);
        const uint4 m2 = *reinterpret_cast<const uint4*>(&sB[2][pd[2]][0]);
        const uint4 m3 = *reinterpret_cast<const uint4*>(&sB[3][pd[3]][0]);
        const uint4 m4 = *reinterpret_cast<const uint4*>(&sB[4][pd[4]][0]);
        const uint4 m5 = *reinterpret_cast<const uint4*>(&sB[5][pd[5]][0]);
        const uint4 m6 = *reinterpret_cast<const uint4*>(&sB[6][pd[6]][0]);

        unsigned pm[TW];
        #pragma unroll
        for (int w = 0; w < TW; w++) {
            const int rem = L - (w << 5);
            pm[w] = (rem <= 0) ? 0u : (rem >= 32 ? 0xFFFFFFFFu : ((1u << rem) - 1u));
        }

        int cnt = 0;
        cnt += __popc(m0.x & m1.x & m2.x & m3.x & m4.x & m5.x & m6.x & pm[0]);
        cnt += __popc(m0.y & m1.y & m2.y & m3.y & m4.y & m5.y & m6.y & pm[1]);
        cnt += __popc(m0.z & m1.z & m2.z & m3.z & m4.z & m5.z & m6.z & pm[2]);
        cnt += __popc(m0.w & m1.w & m2.w & m3.w & m4.w & m5.w & m6.w & pm[3]);

        atomicAdd(&g_counts[m * KN + i_rank], cnt);
    }
}

// ---------------------------------------------------------------------------
// FH) fused histogram + finalize (proven). Last-arriving block runs the W1
//     scan; resets scratch for the next graph replay.
// ---------------------------------------------------------------------------
__global__ __launch_bounds__(1024) void kdm_finh(float* __restrict__ out) {
    const int tid = threadIdx.x, lane = tid & 31, wid = tid >> 5;

    cudaGridDependencySynchronize();

    {   // histogram phase
        const int slot = blockIdx.x * 1024 + tid;
        const int v = g_counts[slot];          // dominated count in [0, 8191]
        g_counts[slot] = 0;
        const int delta = (slot >= KN) ? -1 : 1;
        const unsigned mask = __match_any_sync(0xffffffffu, v);
        if ((int)(__ffs(mask) - 1) == lane)
            atomicAdd(&g_hd[v], delta * __popc(mask));
    }

    __threadfence();
    __syncthreads();
    __shared__ bool s_last;
    if (tid == 0) s_last = (atomicAdd(&g_ctr, 1u) == gridDim.x - 1);
    __syncthreads();
    if (!s_last) return;
    __threadfence();

    __shared__ int wsum[32];
    const int base = tid * 8;
    int d[8], tot = 0;
    #pragma unroll
    for (int k = 0; k < 8; k++) {
        d[k] = g_hd[base + k];
        g_hd[base + k] = 0;
        tot += d[k];
    }

    int v = tot;
    #pragma unroll
    for (int off = 1; off < 32; off <<= 1) {
        const int n = __shfl_up_sync(0xffffffffu, v, off);
        if (lane >= off) v += n;
    }
    if (lane == 31) wsum[wid] = v;
    __syncthreads();
    if (wid == 0) {
        int w = wsum[lane];
        #pragma unroll
        for (int off = 1; off < 32; off <<= 1) {
            const int n = __shfl_up_sync(0xffffffffu, w, off);
            if (lane >= off) w += n;
        }
        wsum[lane] = w;
    }
    __syncthreads();

    const int excl = v - tot + (wid ? wsum[wid - 1] : 0);
    int run = excl, acc = 0;
    #pragma unroll
    for (int k = 0; k < 8; k++) {
        run += d[k];
        acc += (run >= 0) ? run : -run;
    }

    #pragma unroll
    for (int off = 16; off; off >>= 1) acc += __shfl_down_sync(0xffffffffu, acc, off);
    __syncthreads();
    if (lane == 0) wsum[wid] = acc;
    __syncthreads();
    if (wid == 0) {
        int r = wsum[lane];
        #pragma unroll
        for (int off = 16; off; off >>= 1) r += __shfl_down_sync(0xffffffffu, r, off);
        if (lane == 0) {
            out[0] = (float)r / ((float)KN * (float)(KN - 1));
            g_ctr = 0;   // reset for next graph replay
        }
    }
}

// ---------------------------------------------------------------------------
template <typename F, typename... Args>
static void launch_pdl(F f, dim3 grid, dim3 block, Args... args) {
    cudaLaunchConfig_t cfg = {};
    cfg.gridDim  = grid;
    cfg.blockDim = block;
    cfg.dynamicSmemBytes = 0;
    cfg.stream = 0;
    cudaLaunchAttribute attr[1];
    attr[0].id = cudaLaunchAttributeProgrammaticStreamSerialization;
    attr[0].val.programmaticStreamSerializationAllowed = 1;
    cfg.attrs = attr;
    cfg.numAttrs = 1;
    cudaLaunchKernelEx(&cfg, f, args...);
}

extern "C" void kernel_launch(void* const* d_in, const int* in_sizes, int n_in,
                              void* d_out, int out_size) {
    const float* X  = (const float*)d_in[0];
    const float* Xh = (const float*)d_in[1];
    float* out = (float*)d_out;

    kdm_sort_seg<<<dim3(NSEG, 16), 256>>>(X, Xh);
    launch_pdl(kdm_rank, dim3(KN / 256, 16), dim3(256));
    launch_pdl(kdm_prep, dim3(NTILE, 7, 2),  dim3(128));
    launch_pdl(kdm_dom,  dim3(DOMB, 2),      dim3(256));
    launch_pdl(kdm_finh, dim3(2 * KN / 1024), dim3(1024), out);
}